// round 15
// baseline (speedup 1.0000x reference)
#include <cuda_runtime.h>
#include <cuda_bf16.h>
#include <cstdint>

// Problem constants (fixed shapes for this problem)
#define B_   4
#define L_   2048
#define H_   8
#define D_   64
#define SK   40      // sample_k
#define U_   40      // u
#define BH   32      // B_*H_
#define SCALE 0.125f // 1/sqrt(64)
#define NT3  8       // k-tiles for context partials
#define NCHUNK 4
#define CROWS  512   // K rows per smem chunk
#define PADW   68    // padded words per K row in smem (272B, 16B-aligned)

// Scratch (device globals — no allocation allowed)
__device__ int   g_sidx[L_ * SK];              // chunk-bucketed sample indices per q
__device__ int   g_soff[L_ * (NCHUNK + 1)];    // per-q chunk offsets into g_sidx
__device__ float g_pmx[NCHUNK][BH * L_];       // per-chunk max partials
__device__ float g_psm[NCHUNK][BH * L_];       // per-chunk sum partials
__device__ int   g_top[BH * U_];               // 5 KB
__device__ float g_S[(size_t)BH * U_ * L_];    // 10.5 MB: scores -> normalized suffix attn
__device__ float g_C[NT3 * BH * U_ * D_];      // 2.6 MB: context partials

// ---------------------------------------------------------------------------
// K0: bucket each query's 40 sample indices by 512-row chunk. Register-only.
// ---------------------------------------------------------------------------
__global__ __launch_bounds__(256) void k0_prep(const int* __restrict__ idx) {
    int q = blockIdx.x * 256 + threadIdx.x;
    if (q >= L_) return;
    const int* ip = idx + q * SK;
    int v[SK];
    int c0 = 0, c1 = 0, c2 = 0, c3 = 0;
#pragma unroll
    for (int s = 0; s < SK; s++) {
        v[s] = __ldg(ip + s);
        int ch = v[s] >> 9;
        c0 += (ch == 0); c1 += (ch == 1); c2 += (ch == 2); c3 += (ch == 3);
    }
    int o0 = 0, o1 = c0, o2 = c0 + c1, o3 = c0 + c1 + c2;
    g_soff[q * 5 + 0] = 0;
    g_soff[q * 5 + 1] = o1;
    g_soff[q * 5 + 2] = o2;
    g_soff[q * 5 + 3] = o3;
    g_soff[q * 5 + 4] = SK;
#pragma unroll
    for (int s = 0; s < SK; s++) {
        int j = v[s]; int ch = j >> 9; int pos;
        if      (ch == 0) pos = o0++;
        else if (ch == 1) pos = o1++;
        else if (ch == 2) pos = o2++;
        else              pos = o3++;
        g_sidx[q * SK + pos] = j;
    }
}

// ---------------------------------------------------------------------------
// K1: per-(bh,chunk) block stages K chunk in smem; warps walk 64 queries.
// 2-lane groups: each lane holds 32 Q dims (8 float4) -> 16 samples/iter,
// 1 reduce-shfl per iter. Writes per-chunk (max,sum) partials, deterministic.
// ---------------------------------------------------------------------------
__global__ __launch_bounds__(1024, 1) void k1_sample(const float* __restrict__ Q,
                                                     const float* __restrict__ K) {
    extern __shared__ float s_k[];        // CROWS * PADW floats
    int bh    = blockIdx.x >> 2;
    int chunk = blockIdx.x & 3;
    int b = bh >> 3, h = bh & 7;
    int c0 = chunk * CROWS;
    int tid  = threadIdx.x;
    int lane = tid & 31, w = tid >> 5;
    int g = lane >> 1;                    // 16 groups (one sample each per iter)
    int r = lane & 1;                     // pair lane: float4 slots m*2+r

    // stage chunk: K[b, c0+row, h, :] -> smem rows padded to 68 words
    for (int i = tid; i < CROWS * 16; i += 1024) {
        int row = i >> 4, f4 = i & 15;
        const float4* src = (const float4*)(K + ((size_t)(b * L_ + c0 + row) * H_ + h) * D_) + f4;
        *(float4*)(s_k + row * PADW + f4 * 4) = *src;
    }
    __syncthreads();

    int outbase = bh * L_;
    for (int qq = 0; qq < 64; qq++) {
        int q = w * 64 + qq;
        const float4* qp = (const float4*)(Q + ((size_t)(b * L_ + q) * H_ + h) * D_);
        float4 qv[8];
#pragma unroll
        for (int m = 0; m < 8; m++) qv[m] = qp[m * 2 + r];

        int start = g_soff[q * 5 + chunk];
        int cnt   = g_soff[q * 5 + chunk + 1] - start;

        int j0 = 0, j1 = 0;
        if (lane < cnt)      j0 = g_sidx[q * SK + start + lane];
        if (lane + 32 < cnt) j1 = g_sidx[q * SK + start + lane + 32];

        float mx = -1e30f, sm = 0.f;
        int iters = (cnt + 15) >> 4;      // 1..3
        for (int t = 0; t < iters; t++) {
            int sl = t * 16 + g;
            int j = (t < 2) ? __shfl_sync(0xffffffffu, j0, sl)
                            : __shfl_sync(0xffffffffu, j1, sl - 32);
            bool act = (sl < cnt);
            float p = 0.f;
            if (act) {
                const float4* kr = (const float4*)(s_k + (j - c0) * PADW);
#pragma unroll
                for (int m = 0; m < 8; m++) {
                    float4 kv = kr[m * 2 + r];
                    p += qv[m].x * kv.x + qv[m].y * kv.y
                       + qv[m].z * kv.z + qv[m].w * kv.w;
                }
            }
            p += __shfl_xor_sync(0xffffffffu, p, 1);   // pair reduce
            if (act) { mx = fmaxf(mx, p); if (r == 0) sm += p; }
        }
        // cross-group reduce (sm nonzero only on even lanes -> sum is exact)
        mx = fmaxf(mx, __shfl_xor_sync(0xffffffffu, mx, 2));
        mx = fmaxf(mx, __shfl_xor_sync(0xffffffffu, mx, 4));
        mx = fmaxf(mx, __shfl_xor_sync(0xffffffffu, mx, 8));
        mx = fmaxf(mx, __shfl_xor_sync(0xffffffffu, mx, 16));
        sm += __shfl_xor_sync(0xffffffffu, sm, 2);
        sm += __shfl_xor_sync(0xffffffffu, sm, 4);
        sm += __shfl_xor_sync(0xffffffffu, sm, 8);
        sm += __shfl_xor_sync(0xffffffffu, sm, 16);
        if (lane == 0) {
            g_pmx[chunk][outbase + q] = mx;
            g_psm[chunk][outbase + q] = sm;
        }
    }
}

// ---------------------------------------------------------------------------
// K2: combine chunk partials -> M, then register-resident iterative top-40.
// Order matches jax.lax.top_k: value desc, ties -> lower index. One block/(b,h).
// ---------------------------------------------------------------------------
__global__ __launch_bounds__(256) void k2_topk() {
    int bh = blockIdx.x, tid = threadIdx.x;
    int lane = tid & 31, w = tid >> 5;
    float v[8];
#pragma unroll
    for (int jj = 0; jj < 8; jj++) {
        int q = tid + jj * 256;
        float mx = g_pmx[0][bh * L_ + q];
        float sm = g_psm[0][bh * L_ + q];
#pragma unroll
        for (int c = 1; c < 4; c++) {
            mx = fmaxf(mx, g_pmx[c][bh * L_ + q]);
            sm += g_psm[c][bh * L_ + q];
        }
        v[jj] = mx - sm * (1.0f / (float)L_);
    }
    __shared__ unsigned long long wbest[8];
    for (int t = 0; t < U_; t++) {
        float bv = v[0]; int bj = 0;
#pragma unroll
        for (int jj = 1; jj < 8; jj++)
            if (v[jj] > bv) { bv = v[jj]; bj = jj; }   // strict > keeps lower q on ties
        unsigned int ub = __float_as_uint(bv);
        ub = (ub & 0x80000000u) ? ~ub : (ub | 0x80000000u);   // order-preserving map
        int q = tid + bj * 256;
        unsigned long long key =
            ((unsigned long long)ub << 32) | (unsigned)(L_ - 1 - q); // tie -> smaller q wins
#pragma unroll
        for (int off = 16; off > 0; off >>= 1) {
            unsigned long long o = __shfl_xor_sync(0xffffffffu, key, off);
            if (o > key) key = o;
        }
        if (lane == 0) wbest[w] = key;
        __syncthreads();
        unsigned long long best = wbest[0];
#pragma unroll
        for (int i = 1; i < 8; i++) if (wbest[i] > best) best = wbest[i];
        int bq = L_ - 1 - (int)(best & 0xffffffffu);
        if (tid == 0) g_top[bh * U_ + t] = bq;
        if ((bq & 255) == tid) {
            int cj = bq >> 8;
#pragma unroll
            for (int jj = 0; jj < 8; jj++) if (jj == cj) v[jj] = -1e30f;
        }
        __syncthreads();
    }
}

// ---------------------------------------------------------------------------
// K3a: scores[u,k] = (Q_reduce[u,:] . K[k,:]) * SCALE  -> g_S
// 256 threads: 32 k-lanes (4 k each) x 8 u-groups (5 u each). d-loop in
// float4 steps: 5 broadcast LDS.128 (Q) + 16 conflict-free LDS.32 (K) + 80 FFMA.
// SCALE folded into Qs at staging time.
// ---------------------------------------------------------------------------
__global__ __launch_bounds__(256) void k3a_scores(const float* __restrict__ Q,
                                                  const float* __restrict__ K) {
    int bh   = blockIdx.x >> 4;
    int tile = blockIdx.x & 15;
    int b = bh >> 3, h = bh & 7;
    int tid = threadIdx.x;
    int kx = tid & 31;        // k lane: owns k = kx + 32*j, j=0..3
    int uy = tid >> 5;        // u group: owns u = uy*5 + i, i=0..4

    __shared__ float Qs[U_ * D_];       // 10 KB
    __shared__ float Ks[128 * 65];      // 33.3 KB

    for (int i = tid; i < U_ * D_; i += 256) {
        int u = i >> 6, d = i & 63;
        int qi = g_top[bh * U_ + u];
        Qs[i] = Q[((size_t)(b * L_ + qi) * H_ + h) * D_ + d] * SCALE;
    }
    int k0 = tile * 128;
    for (int i = tid; i < 128 * D_; i += 256) {
        int kk = i >> 6, d = i & 63;
        Ks[kk * 65 + d] = K[((size_t)(b * L_ + k0 + kk) * H_ + h) * D_ + d];
    }
    __syncthreads();

    float acc[20];
#pragma unroll
    for (int a = 0; a < 20; a++) acc[a] = 0.f;

    for (int d4 = 0; d4 < 16; d4++) {
        float4 q4[5];
#pragma unroll
        for (int i = 0; i < 5; i++)
            q4[i] = *(const float4*)(Qs + (uy * 5 + i) * 64 + d4 * 4);
#pragma unroll
        for (int j = 0; j < 4; j++) {
            const float* kp = Ks + (kx + 32 * j) * 65 + d4 * 4;
            float k0v = kp[0], k1v = kp[1], k2v = kp[2], k3v = kp[3];
#pragma unroll
            for (int i = 0; i < 5; i++)
                acc[i * 4 + j] += q4[i].x * k0v + q4[i].y * k1v
                                + q4[i].z * k2v + q4[i].w * k3v;
        }
    }
#pragma unroll
    for (int i = 0; i < 5; i++) {
        int u = uy * 5 + i;
        float* dst = g_S + ((size_t)(bh * U_ + u)) * L_ + k0 + kx;
#pragma unroll
        for (int j = 0; j < 4; j++)
            dst[32 * j] = acc[i * 4 + j];
    }
}

// ---------------------------------------------------------------------------
// K3b: per row (bh,u): softmax + suffix-sum, normalized, in place.
// Register-resident: float4 loads, warp shuffles, 2 barriers total.
// ---------------------------------------------------------------------------
__global__ __launch_bounds__(256) void k3b_scan() {
    int row = blockIdx.x, tid = threadIdx.x;
    int lane = tid & 31, w = tid >> 5;
    float4* p4 = (float4*)(g_S + (size_t)row * L_) + tid * 2;
    float4 a = p4[0], b = p4[1];

    float m = fmaxf(fmaxf(fmaxf(a.x, a.y), fmaxf(a.z, a.w)),
                    fmaxf(fmaxf(b.x, b.y), fmaxf(b.z, b.w)));
#pragma unroll
    for (int off = 16; off > 0; off >>= 1)
        m = fmaxf(m, __shfl_xor_sync(0xffffffffu, m, off));
    __shared__ float wmax[8], wsum[8];
    if (lane == 0) wmax[w] = m;
    __syncthreads();
    float rm = wmax[0];
#pragma unroll
    for (int i = 1; i < 8; i++) rm = fmaxf(rm, wmax[i]);

    // exp + suffix within the thread's 8 elements (descending j)
    float s = __expf(b.w - rm); b.w = s;
    s += __expf(b.z - rm); b.z = s;
    s += __expf(b.y - rm); b.y = s;
    s += __expf(b.x - rm); b.x = s;
    s += __expf(a.w - rm); a.w = s;
    s += __expf(a.z - rm); a.z = s;
    s += __expf(a.y - rm); a.y = s;
    s += __expf(a.x - rm); a.x = s;
    float chunk = s;

    // warp inclusive suffix scan of chunk sums
    float c = chunk;
#pragma unroll
    for (int off = 1; off < 32; off <<= 1) {
        float vv = __shfl_down_sync(0xffffffffu, c, off);
        if (lane + off < 32) c += vv;
    }
    if (lane == 0) wsum[w] = c;           // warp total
    __syncthreads();
    float total = 0.f, after = 0.f;
#pragma unroll
    for (int i = 7; i >= 0; i--) { total += wsum[i]; if (i > w) after += wsum[i]; }
    float add  = (c - chunk) + after;     // suffix strictly after this thread's 8
    float invZ = 1.0f / total;

    a.x = (a.x + add) * invZ; a.y = (a.y + add) * invZ;
    a.z = (a.z + add) * invZ; a.w = (a.w + add) * invZ;
    b.x = (b.x + add) * invZ; b.y = (b.y + add) * invZ;
    b.z = (b.z + add) * invZ; b.w = (b.w + add) * invZ;
    p4[0] = a; p4[1] = b;
}

// ---------------------------------------------------------------------------
// K3c: context partials: C_part[tile] = S[:, ktile] @ V[ktile, :]
// Register tiling: 16 d-lanes (4 d via LDS.128) x 8 u-threads (5 u each).
// ---------------------------------------------------------------------------
__global__ __launch_bounds__(128) void k3c_ctx(const float* __restrict__ V) {
    int bh   = blockIdx.x >> 3;
    int tile = blockIdx.x & 7;
    int b = bh >> 3, h = bh & 7;
    int tid = threadIdx.x;
    int dx = tid & 15;        // owns d = dx*4 .. dx*4+3
    int uy = tid >> 4;        // owns u = uy*5 + i, i=0..4

    __shared__ float Vs[64 * 64];   // 16 KB
    __shared__ float Ss[U_ * 64];   // 10 KB

    float4 acc[5];
#pragma unroll
    for (int i = 0; i < 5; i++) acc[i] = make_float4(0.f, 0.f, 0.f, 0.f);

    for (int c = 0; c < 4; c++) {
        int k0 = tile * 256 + c * 64;
        __syncthreads();
        for (int i = tid; i < 64 * 16; i += 128) {
            int kk = i >> 4, f = i & 15;
            float4 vv = *((const float4*)(V + ((size_t)(b * L_ + k0 + kk) * H_ + h) * D_) + f);
            *(float4*)(Vs + kk * 64 + f * 4) = vv;
        }
        for (int i = tid; i < U_ * 64; i += 128) {
            int u = i >> 6, kk = i & 63;
            Ss[i] = g_S[((size_t)(bh * U_ + u)) * L_ + k0 + kk];
        }
        __syncthreads();
        for (int k = 0; k < 64; k++) {
            float4 v = *(const float4*)(Vs + k * 64 + dx * 4);
#pragma unroll
            for (int i = 0; i < 5; i++) {
                float sv = Ss[(uy * 5 + i) * 64 + k];
                acc[i].x += sv * v.x; acc[i].y += sv * v.y;
                acc[i].z += sv * v.z; acc[i].w += sv * v.w;
            }
        }
    }
#pragma unroll
    for (int i = 0; i < 5; i++) {
        int u = uy * 5 + i;
        *(float4*)(g_C + (size_t)tile * (BH * U_ * D_) + (bh * U_ + u) * D_ + dx * 4) = acc[i];
    }
}

// ---------------------------------------------------------------------------
// K3r: reduce partials -> out
// ---------------------------------------------------------------------------
__global__ __launch_bounds__(256) void k3r_reduce(float* __restrict__ out) {
    int i = blockIdx.x * 256 + threadIdx.x;
    float s = 0.f;
#pragma unroll
    for (int t = 0; t < NT3; t++) s += g_C[(size_t)t * (BH * U_ * D_) + i];
    out[i] = s;
}

// ---------------------------------------------------------------------------
extern "C" void kernel_launch(void* const* d_in, const int* in_sizes, int n_in,
                              void* d_out, int out_size) {
    const float* Q   = (const float*)d_in[0];
    const float* K   = (const float*)d_in[1];
    const float* V   = (const float*)d_in[2];
    const int*   idx = (const int*)d_in[3];
    float* out = (float*)d_out;

    cudaFuncSetAttribute(k1_sample, cudaFuncAttributeMaxDynamicSharedMemorySize,
                         CROWS * PADW * 4);

    k0_prep<<<(L_ + 255) / 256, 256>>>(idx);
    k1_sample<<<BH * NCHUNK, 1024, CROWS * PADW * 4>>>(Q, K);
    k2_topk<<<BH, 256>>>();
    k3a_scores<<<BH * 16, 256>>>(Q, K);
    k3b_scan<<<BH * U_, 256>>>();
    k3c_ctx<<<BH * NT3, 128>>>(V);
    k3r_reduce<<<(BH * U_ * D_) / 256, 256>>>(out);
}

// round 16
// speedup vs baseline: 1.0071x; 1.0071x over previous
#include <cuda_runtime.h>
#include <cuda_bf16.h>
#include <cstdint>

// Problem constants (fixed shapes for this problem)
#define B_   4
#define L_   2048
#define H_   8
#define D_   64
#define SK   40      // sample_k
#define U_   40      // u
#define BH   32      // B_*H_
#define SCALE 0.125f // 1/sqrt(64)
#define NT3  8       // k-tiles for context partials
#define NCHUNK 4
#define CROWS  512   // K rows per smem chunk
#define PADW   68    // padded words per K row in smem (272B, 16B-aligned)

// Scratch (device globals — no allocation allowed)
__device__ int   g_sidx[L_ * SK];              // chunk-bucketed sample indices per q
__device__ int   g_soff[L_ * (NCHUNK + 1)];    // per-q chunk offsets into g_sidx
__device__ float g_pmx[NCHUNK][BH * L_];       // per-chunk max partials
__device__ float g_psm[NCHUNK][BH * L_];       // per-chunk sum partials
__device__ int   g_top[BH * U_];               // 5 KB
__device__ float g_S[(size_t)BH * U_ * L_];    // 10.5 MB: scores -> normalized suffix attn
__device__ float g_C[NT3 * BH * U_ * D_];      // 2.6 MB: context partials

// ---------------------------------------------------------------------------
// K0: bucket each query's 40 sample indices by 512-row chunk. Register-only.
// ---------------------------------------------------------------------------
__global__ __launch_bounds__(256) void k0_prep(const int* __restrict__ idx) {
    int q = blockIdx.x * 256 + threadIdx.x;
    if (q >= L_) return;
    const int* ip = idx + q * SK;
    int v[SK];
    int c0 = 0, c1 = 0, c2 = 0, c3 = 0;
#pragma unroll
    for (int s = 0; s < SK; s++) {
        v[s] = __ldg(ip + s);
        int ch = v[s] >> 9;
        c0 += (ch == 0); c1 += (ch == 1); c2 += (ch == 2); c3 += (ch == 3);
    }
    int o0 = 0, o1 = c0, o2 = c0 + c1, o3 = c0 + c1 + c2;
    g_soff[q * 5 + 0] = 0;
    g_soff[q * 5 + 1] = o1;
    g_soff[q * 5 + 2] = o2;
    g_soff[q * 5 + 3] = o3;
    g_soff[q * 5 + 4] = SK;
#pragma unroll
    for (int s = 0; s < SK; s++) {
        int j = v[s]; int ch = j >> 9; int pos;
        if      (ch == 0) pos = o0++;
        else if (ch == 1) pos = o1++;
        else if (ch == 2) pos = o2++;
        else              pos = o3++;
        g_sidx[q * SK + pos] = j;
    }
}

// ---------------------------------------------------------------------------
// K1: per-(bh,chunk) block stages K chunk in smem; warps walk 64 queries.
// 2-lane groups: each lane holds 32 Q dims (8 float4) -> 16 samples/iter,
// 1 reduce-shfl per iter. Writes per-chunk (max,sum) partials, deterministic.
// ---------------------------------------------------------------------------
__global__ __launch_bounds__(1024, 1) void k1_sample(const float* __restrict__ Q,
                                                     const float* __restrict__ K) {
    extern __shared__ float s_k[];        // CROWS * PADW floats
    int bh    = blockIdx.x >> 2;
    int chunk = blockIdx.x & 3;
    int b = bh >> 3, h = bh & 7;
    int c0 = chunk * CROWS;
    int tid  = threadIdx.x;
    int lane = tid & 31, w = tid >> 5;
    int g = lane >> 1;                    // 16 groups (one sample each per iter)
    int r = lane & 1;                     // pair lane: float4 slots m*2+r

    // stage chunk: K[b, c0+row, h, :] -> smem rows padded to 68 words
    for (int i = tid; i < CROWS * 16; i += 1024) {
        int row = i >> 4, f4 = i & 15;
        const float4* src = (const float4*)(K + ((size_t)(b * L_ + c0 + row) * H_ + h) * D_) + f4;
        *(float4*)(s_k + row * PADW + f4 * 4) = *src;
    }
    __syncthreads();

    int outbase = bh * L_;
    for (int qq = 0; qq < 64; qq++) {
        int q = w * 64 + qq;
        const float4* qp = (const float4*)(Q + ((size_t)(b * L_ + q) * H_ + h) * D_);
        float4 qv[8];
#pragma unroll
        for (int m = 0; m < 8; m++) qv[m] = qp[m * 2 + r];

        int start = g_soff[q * 5 + chunk];
        int cnt   = g_soff[q * 5 + chunk + 1] - start;

        int j0 = 0, j1 = 0;
        if (lane < cnt)      j0 = g_sidx[q * SK + start + lane];
        if (lane + 32 < cnt) j1 = g_sidx[q * SK + start + lane + 32];

        float mx = -1e30f, sm = 0.f;
        int iters = (cnt + 15) >> 4;      // 1..3
        for (int t = 0; t < iters; t++) {
            int sl = t * 16 + g;
            int j = (t < 2) ? __shfl_sync(0xffffffffu, j0, sl)
                            : __shfl_sync(0xffffffffu, j1, sl - 32);
            bool act = (sl < cnt);
            float p = 0.f;
            if (act) {
                const float4* kr = (const float4*)(s_k + (j - c0) * PADW);
#pragma unroll
                for (int m = 0; m < 8; m++) {
                    float4 kv = kr[m * 2 + r];
                    p += qv[m].x * kv.x + qv[m].y * kv.y
                       + qv[m].z * kv.z + qv[m].w * kv.w;
                }
            }
            p += __shfl_xor_sync(0xffffffffu, p, 1);   // pair reduce
            if (act) { mx = fmaxf(mx, p); if (r == 0) sm += p; }
        }
        // cross-group reduce (sm nonzero only on even lanes -> sum is exact)
        mx = fmaxf(mx, __shfl_xor_sync(0xffffffffu, mx, 2));
        mx = fmaxf(mx, __shfl_xor_sync(0xffffffffu, mx, 4));
        mx = fmaxf(mx, __shfl_xor_sync(0xffffffffu, mx, 8));
        mx = fmaxf(mx, __shfl_xor_sync(0xffffffffu, mx, 16));
        sm += __shfl_xor_sync(0xffffffffu, sm, 2);
        sm += __shfl_xor_sync(0xffffffffu, sm, 4);
        sm += __shfl_xor_sync(0xffffffffu, sm, 8);
        sm += __shfl_xor_sync(0xffffffffu, sm, 16);
        if (lane == 0) {
            g_pmx[chunk][outbase + q] = mx;
            g_psm[chunk][outbase + q] = sm;
        }
    }
}

// ---------------------------------------------------------------------------
// K2: combine chunk partials -> M, then register-resident iterative top-40.
// Order matches jax.lax.top_k: value desc, ties -> lower index. One block/(b,h).
// ---------------------------------------------------------------------------
__global__ __launch_bounds__(256) void k2_topk() {
    int bh = blockIdx.x, tid = threadIdx.x;
    int lane = tid & 31, w = tid >> 5;
    float v[8];
#pragma unroll
    for (int jj = 0; jj < 8; jj++) {
        int q = tid + jj * 256;
        float mx = g_pmx[0][bh * L_ + q];
        float sm = g_psm[0][bh * L_ + q];
#pragma unroll
        for (int c = 1; c < 4; c++) {
            mx = fmaxf(mx, g_pmx[c][bh * L_ + q]);
            sm += g_psm[c][bh * L_ + q];
        }
        v[jj] = mx - sm * (1.0f / (float)L_);
    }
    __shared__ unsigned long long wbest[8];
    for (int t = 0; t < U_; t++) {
        float bv = v[0]; int bj = 0;
#pragma unroll
        for (int jj = 1; jj < 8; jj++)
            if (v[jj] > bv) { bv = v[jj]; bj = jj; }   // strict > keeps lower q on ties
        unsigned int ub = __float_as_uint(bv);
        ub = (ub & 0x80000000u) ? ~ub : (ub | 0x80000000u);   // order-preserving map
        int q = tid + bj * 256;
        unsigned long long key =
            ((unsigned long long)ub << 32) | (unsigned)(L_ - 1 - q); // tie -> smaller q wins
#pragma unroll
        for (int off = 16; off > 0; off >>= 1) {
            unsigned long long o = __shfl_xor_sync(0xffffffffu, key, off);
            if (o > key) key = o;
        }
        if (lane == 0) wbest[w] = key;
        __syncthreads();
        unsigned long long best = wbest[0];
#pragma unroll
        for (int i = 1; i < 8; i++) if (wbest[i] > best) best = wbest[i];
        int bq = L_ - 1 - (int)(best & 0xffffffffu);
        if (tid == 0) g_top[bh * U_ + t] = bq;
        if ((bq & 255) == tid) {
            int cj = bq >> 8;
#pragma unroll
            for (int jj = 0; jj < 8; jj++) if (jj == cj) v[jj] = -1e30f;
        }
        __syncthreads();
    }
}

// ---------------------------------------------------------------------------
// K3a: scores[u,k] = (Q_reduce[u,:] . K[k,:]) * SCALE  -> g_S
// 256 threads: 32 k-lanes (4 k each) x 8 u-groups (5 u each). d-loop in
// float4 steps: 5 broadcast LDS.128 (Q) + 16 conflict-free LDS.32 (K) + 80 FFMA.
// SCALE folded into Qs at staging time.
// ---------------------------------------------------------------------------
__global__ __launch_bounds__(256) void k3a_scores(const float* __restrict__ Q,
                                                  const float* __restrict__ K) {
    int bh   = blockIdx.x >> 4;
    int tile = blockIdx.x & 15;
    int b = bh >> 3, h = bh & 7;
    int tid = threadIdx.x;
    int kx = tid & 31;        // k lane: owns k = kx + 32*j, j=0..3
    int uy = tid >> 5;        // u group: owns u = uy*5 + i, i=0..4

    __shared__ float Qs[U_ * D_];       // 10 KB
    __shared__ float Ks[128 * 65];      // 33.3 KB

    for (int i = tid; i < U_ * D_; i += 256) {
        int u = i >> 6, d = i & 63;
        int qi = g_top[bh * U_ + u];
        Qs[i] = Q[((size_t)(b * L_ + qi) * H_ + h) * D_ + d] * SCALE;
    }
    int k0 = tile * 128;
    for (int i = tid; i < 128 * D_; i += 256) {
        int kk = i >> 6, d = i & 63;
        Ks[kk * 65 + d] = K[((size_t)(b * L_ + k0 + kk) * H_ + h) * D_ + d];
    }
    __syncthreads();

    float acc[20];
#pragma unroll
    for (int a = 0; a < 20; a++) acc[a] = 0.f;

    for (int d4 = 0; d4 < 16; d4++) {
        float4 q4[5];
#pragma unroll
        for (int i = 0; i < 5; i++)
            q4[i] = *(const float4*)(Qs + (uy * 5 + i) * 64 + d4 * 4);
#pragma unroll
        for (int j = 0; j < 4; j++) {
            const float* kp = Ks + (kx + 32 * j) * 65 + d4 * 4;
            float k0v = kp[0], k1v = kp[1], k2v = kp[2], k3v = kp[3];
#pragma unroll
            for (int i = 0; i < 5; i++)
                acc[i * 4 + j] += q4[i].x * k0v + q4[i].y * k1v
                                + q4[i].z * k2v + q4[i].w * k3v;
        }
    }
#pragma unroll
    for (int i = 0; i < 5; i++) {
        int u = uy * 5 + i;
        float* dst = g_S + ((size_t)(bh * U_ + u)) * L_ + k0 + kx;
#pragma unroll
        for (int j = 0; j < 4; j++)
            dst[32 * j] = acc[i * 4 + j];
    }
}

// ---------------------------------------------------------------------------
// K3b: per row (bh,u): softmax + suffix-sum, normalized, in place.
// Register-resident: float4 loads, warp shuffles, 2 barriers total.
// ---------------------------------------------------------------------------
__global__ __launch_bounds__(256) void k3b_scan() {
    int row = blockIdx.x, tid = threadIdx.x;
    int lane = tid & 31, w = tid >> 5;
    float4* p4 = (float4*)(g_S + (size_t)row * L_) + tid * 2;
    float4 a = p4[0], b = p4[1];

    float m = fmaxf(fmaxf(fmaxf(a.x, a.y), fmaxf(a.z, a.w)),
                    fmaxf(fmaxf(b.x, b.y), fmaxf(b.z, b.w)));
#pragma unroll
    for (int off = 16; off > 0; off >>= 1)
        m = fmaxf(m, __shfl_xor_sync(0xffffffffu, m, off));
    __shared__ float wmax[8], wsum[8];
    if (lane == 0) wmax[w] = m;
    __syncthreads();
    float rm = wmax[0];
#pragma unroll
    for (int i = 1; i < 8; i++) rm = fmaxf(rm, wmax[i]);

    // exp + suffix within the thread's 8 elements (descending j)
    float s = __expf(b.w - rm); b.w = s;
    s += __expf(b.z - rm); b.z = s;
    s += __expf(b.y - rm); b.y = s;
    s += __expf(b.x - rm); b.x = s;
    s += __expf(a.w - rm); a.w = s;
    s += __expf(a.z - rm); a.z = s;
    s += __expf(a.y - rm); a.y = s;
    s += __expf(a.x - rm); a.x = s;
    float chunk = s;

    // warp inclusive suffix scan of chunk sums
    float c = chunk;
#pragma unroll
    for (int off = 1; off < 32; off <<= 1) {
        float vv = __shfl_down_sync(0xffffffffu, c, off);
        if (lane + off < 32) c += vv;
    }
    if (lane == 0) wsum[w] = c;           // warp total
    __syncthreads();
    float total = 0.f, after = 0.f;
#pragma unroll
    for (int i = 7; i >= 0; i--) { total += wsum[i]; if (i > w) after += wsum[i]; }
    float add  = (c - chunk) + after;     // suffix strictly after this thread's 8
    float invZ = 1.0f / total;

    a.x = (a.x + add) * invZ; a.y = (a.y + add) * invZ;
    a.z = (a.z + add) * invZ; a.w = (a.w + add) * invZ;
    b.x = (b.x + add) * invZ; b.y = (b.y + add) * invZ;
    b.z = (b.z + add) * invZ; b.w = (b.w + add) * invZ;
    p4[0] = a; p4[1] = b;
}

// ---------------------------------------------------------------------------
// K3c: context partials: C_part[tile] = S[:, ktile] @ V[ktile, :]
// Register tiling: 16 d-lanes (4 d via LDS.128) x 8 u-threads (5 u each).
// ---------------------------------------------------------------------------
__global__ __launch_bounds__(128) void k3c_ctx(const float* __restrict__ V) {
    int bh   = blockIdx.x >> 3;
    int tile = blockIdx.x & 7;
    int b = bh >> 3, h = bh & 7;
    int tid = threadIdx.x;
    int dx = tid & 15;        // owns d = dx*4 .. dx*4+3
    int uy = tid >> 4;        // owns u = uy*5 + i, i=0..4

    __shared__ float Vs[64 * 64];   // 16 KB
    __shared__ float Ss[U_ * 64];   // 10 KB

    float4 acc[5];
#pragma unroll
    for (int i = 0; i < 5; i++) acc[i] = make_float4(0.f, 0.f, 0.f, 0.f);

    for (int c = 0; c < 4; c++) {
        int k0 = tile * 256 + c * 64;
        __syncthreads();
        for (int i = tid; i < 64 * 16; i += 128) {
            int kk = i >> 4, f = i & 15;
            float4 vv = *((const float4*)(V + ((size_t)(b * L_ + k0 + kk) * H_ + h) * D_) + f);
            *(float4*)(Vs + kk * 64 + f * 4) = vv;
        }
        for (int i = tid; i < U_ * 64; i += 128) {
            int u = i >> 6, kk = i & 63;
            Ss[i] = g_S[((size_t)(bh * U_ + u)) * L_ + k0 + kk];
        }
        __syncthreads();
        for (int k = 0; k < 64; k++) {
            float4 v = *(const float4*)(Vs + k * 64 + dx * 4);
#pragma unroll
            for (int i = 0; i < 5; i++) {
                float sv = Ss[(uy * 5 + i) * 64 + k];
                acc[i].x += sv * v.x; acc[i].y += sv * v.y;
                acc[i].z += sv * v.z; acc[i].w += sv * v.w;
            }
        }
    }
#pragma unroll
    for (int i = 0; i < 5; i++) {
        int u = uy * 5 + i;
        *(float4*)(g_C + (size_t)tile * (BH * U_ * D_) + (bh * U_ + u) * D_ + dx * 4) = acc[i];
    }
}

// ---------------------------------------------------------------------------
// K3r: reduce partials -> out
// ---------------------------------------------------------------------------
__global__ __launch_bounds__(256) void k3r_reduce(float* __restrict__ out) {
    int i = blockIdx.x * 256 + threadIdx.x;
    float s = 0.f;
#pragma unroll
    for (int t = 0; t < NT3; t++) s += g_C[(size_t)t * (BH * U_ * D_) + i];
    out[i] = s;
}

// ---------------------------------------------------------------------------
extern "C" void kernel_launch(void* const* d_in, const int* in_sizes, int n_in,
                              void* d_out, int out_size) {
    const float* Q   = (const float*)d_in[0];
    const float* K   = (const float*)d_in[1];
    const float* V   = (const float*)d_in[2];
    const int*   idx = (const int*)d_in[3];
    float* out = (float*)d_out;

    cudaFuncSetAttribute(k1_sample, cudaFuncAttributeMaxDynamicSharedMemorySize,
                         CROWS * PADW * 4);

    k0_prep<<<(L_ + 255) / 256, 256>>>(idx);
    k1_sample<<<BH * NCHUNK, 1024, CROWS * PADW * 4>>>(Q, K);
    k2_topk<<<BH, 256>>>();
    k3a_scores<<<BH * 16, 256>>>(Q, K);
    k3b_scan<<<BH * U_, 256>>>();
    k3c_ctx<<<BH * NT3, 128>>>(V);
    k3r_reduce<<<(BH * U_ * D_) / 256, 256>>>(out);
}

// round 17
// speedup vs baseline: 1.2365x; 1.2278x over previous
#include <cuda_runtime.h>
#include <cuda_bf16.h>
#include <cstdint>

// Problem constants (fixed shapes for this problem)
#define B_   4
#define L_   2048
#define H_   8
#define D_   64
#define SK   40      // sample_k
#define U_   40      // u
#define BH   32      // B_*H_
#define SCALE 0.125f // 1/sqrt(64)
#define NT3  8       // k-tiles for context partials
#define NCHUNK 4
#define CROWS  512   // K rows per smem chunk
#define PADW   68    // padded words per K row in smem (272B, 16B-aligned)

// Scratch (device globals — no allocation allowed)
__device__ int   g_sidx[L_ * SK];              // chunk-bucketed sample indices per q
__device__ int   g_soff[L_ * (NCHUNK + 1)];    // per-q chunk offsets into g_sidx
__device__ float g_pmx[NCHUNK][BH * L_];       // per-chunk max partials
__device__ float g_psm[NCHUNK][BH * L_];       // per-chunk sum partials
__device__ int   g_top[BH * U_];               // 5 KB
__device__ float g_S[(size_t)BH * U_ * L_];    // 10.5 MB: scores -> normalized suffix attn
__device__ float g_C[NT3 * BH * U_ * D_];      // 2.6 MB: context partials

// ---------------------------------------------------------------------------
// K0: bucket each query's 40 sample indices by 512-row chunk. Register-only.
// ---------------------------------------------------------------------------
__global__ __launch_bounds__(256) void k0_prep(const int* __restrict__ idx) {
    int q = blockIdx.x * 256 + threadIdx.x;
    if (q >= L_) return;
    const int* ip = idx + q * SK;
    int v[SK];
    int c0 = 0, c1 = 0, c2 = 0, c3 = 0;
#pragma unroll
    for (int s = 0; s < SK; s++) {
        v[s] = __ldg(ip + s);
        int ch = v[s] >> 9;
        c0 += (ch == 0); c1 += (ch == 1); c2 += (ch == 2); c3 += (ch == 3);
    }
    int o0 = 0, o1 = c0, o2 = c0 + c1, o3 = c0 + c1 + c2;
    g_soff[q * 5 + 0] = 0;
    g_soff[q * 5 + 1] = o1;
    g_soff[q * 5 + 2] = o2;
    g_soff[q * 5 + 3] = o3;
    g_soff[q * 5 + 4] = SK;
#pragma unroll
    for (int s = 0; s < SK; s++) {
        int j = v[s]; int ch = j >> 9; int pos;
        if      (ch == 0) pos = o0++;
        else if (ch == 1) pos = o1++;
        else if (ch == 2) pos = o2++;
        else              pos = o3++;
        g_sidx[q * SK + pos] = j;
    }
}

// ---------------------------------------------------------------------------
// K1: per-(bh,chunk) block stages K chunk in smem; warps walk 64 queries each,
// computing sampled dots for members of this chunk via 8-lane x 8-dim groups.
// (4 rows per LDS.128 instruction; 8 consecutive lanes sweep a row -> near
// conflict-free.) Writes per-chunk (max,sum) partials — no atomics.
// ---------------------------------------------------------------------------
__global__ __launch_bounds__(1024, 1) void k1_sample(const float* __restrict__ Q,
                                                     const float* __restrict__ K) {
    extern __shared__ float s_k[];        // CROWS * PADW floats
    int bh    = blockIdx.x >> 2;
    int chunk = blockIdx.x & 3;
    int b = bh >> 3, h = bh & 7;
    int c0 = chunk * CROWS;
    int tid  = threadIdx.x;
    int lane = tid & 31, w = tid >> 5;
    int g = lane >> 3;                    // group 0..3 (4 samples in parallel)
    int r = lane & 7;                     // lane-in-group: covers dims r*4.. & 32+r*4..

    // stage chunk: K[b, c0+row, h, :] -> smem rows padded to 68 words
    for (int i = tid; i < CROWS * 16; i += 1024) {
        int row = i >> 4, f4 = i & 15;
        const float4* src = (const float4*)(K + ((size_t)(b * L_ + c0 + row) * H_ + h) * D_) + f4;
        *(float4*)(s_k + row * PADW + f4 * 4) = *src;
    }
    __syncthreads();

    int outbase = bh * L_;
    for (int qq = 0; qq < 64; qq++) {
        int q = w * 64 + qq;
        const float* qp = Q + ((size_t)(b * L_ + q) * H_ + h) * D_;
        float4 qa = *(const float4*)(qp + r * 4);
        float4 qb = *(const float4*)(qp + 32 + r * 4);

        int start = g_soff[q * 5 + chunk];
        int cnt   = g_soff[q * 5 + chunk + 1] - start;

        int j0 = 0, j1 = 0;
        if (lane < cnt)      j0 = g_sidx[q * SK + start + lane];
        if (lane + 32 < cnt) j1 = g_sidx[q * SK + start + lane + 32];

        float mx = -1e30f, sm = 0.f;
        int iters = (cnt + 3) >> 2;
        for (int t = 0; t < iters; t++) {
            int sl = t * 4 + g;
            int j = (t < 8) ? __shfl_sync(0xffffffffu, j0, sl)
                            : __shfl_sync(0xffffffffu, j1, sl - 32);
            bool m = (sl < cnt);
            float p = 0.f;
            if (m) {
                const float* kr = s_k + (j - c0) * PADW;
                float4 ka = *(const float4*)(kr + r * 4);
                float4 kb = *(const float4*)(kr + 32 + r * 4);
                p = qa.x * ka.x + qa.y * ka.y + qa.z * ka.z + qa.w * ka.w
                  + qb.x * kb.x + qb.y * kb.y + qb.z * kb.z + qb.w * kb.w;
            }
            // reduce within 8-lane group (serves 4 pairs per instruction)
            p += __shfl_xor_sync(0xffffffffu, p, 1);
            p += __shfl_xor_sync(0xffffffffu, p, 2);
            p += __shfl_xor_sync(0xffffffffu, p, 4);
            if (m) { mx = fmaxf(mx, p); if (r == 0) sm += p; }
        }
        // cross-group reduce
        mx = fmaxf(mx, __shfl_xor_sync(0xffffffffu, mx, 8));
        mx = fmaxf(mx, __shfl_xor_sync(0xffffffffu, mx, 16));
        sm += __shfl_xor_sync(0xffffffffu, sm, 8);
        sm += __shfl_xor_sync(0xffffffffu, sm, 16);
        if (lane == 0) {
            g_pmx[chunk][outbase + q] = mx;
            g_psm[chunk][outbase + q] = sm;
        }
    }
}

// ---------------------------------------------------------------------------
// K2: combine chunk partials -> M, then register-resident iterative top-40.
// Order matches jax.lax.top_k: value desc, ties -> lower index. One block/(b,h).
// ---------------------------------------------------------------------------
__global__ __launch_bounds__(256) void k2_topk() {
    int bh = blockIdx.x, tid = threadIdx.x;
    int lane = tid & 31, w = tid >> 5;
    float v[8];
#pragma unroll
    for (int jj = 0; jj < 8; jj++) {
        int q = tid + jj * 256;
        float mx = g_pmx[0][bh * L_ + q];
        float sm = g_psm[0][bh * L_ + q];
#pragma unroll
        for (int c = 1; c < 4; c++) {
            mx = fmaxf(mx, g_pmx[c][bh * L_ + q]);
            sm += g_psm[c][bh * L_ + q];
        }
        v[jj] = mx - sm * (1.0f / (float)L_);
    }
    __shared__ unsigned long long wbest[8];
    for (int t = 0; t < U_; t++) {
        float bv = v[0]; int bj = 0;
#pragma unroll
        for (int jj = 1; jj < 8; jj++)
            if (v[jj] > bv) { bv = v[jj]; bj = jj; }   // strict > keeps lower q on ties
        unsigned int ub = __float_as_uint(bv);
        ub = (ub & 0x80000000u) ? ~ub : (ub | 0x80000000u);   // order-preserving map
        int q = tid + bj * 256;
        unsigned long long key =
            ((unsigned long long)ub << 32) | (unsigned)(L_ - 1 - q); // tie -> smaller q wins
#pragma unroll
        for (int off = 16; off > 0; off >>= 1) {
            unsigned long long o = __shfl_xor_sync(0xffffffffu, key, off);
            if (o > key) key = o;
        }
        if (lane == 0) wbest[w] = key;
        __syncthreads();
        unsigned long long best = wbest[0];
#pragma unroll
        for (int i = 1; i < 8; i++) if (wbest[i] > best) best = wbest[i];
        int bq = L_ - 1 - (int)(best & 0xffffffffu);
        if (tid == 0) g_top[bh * U_ + t] = bq;
        if ((bq & 255) == tid) {
            int cj = bq >> 8;
#pragma unroll
            for (int jj = 0; jj < 8; jj++) if (jj == cj) v[jj] = -1e30f;
        }
        __syncthreads();
    }
}

// ---------------------------------------------------------------------------
// K3a: scores[u,k] = (Q_reduce[u,:] . K[k,:]) * SCALE  -> g_S
// 256 threads: 32 k-lanes (4 k each) x 8 u-groups (5 u each). d-loop in
// float4 steps: 5 broadcast LDS.128 (Q) + 16 conflict-free LDS.32 (K) + 80 FFMA.
// SCALE folded into Qs at staging time.
// ---------------------------------------------------------------------------
__global__ __launch_bounds__(256) void k3a_scores(const float* __restrict__ Q,
                                                  const float* __restrict__ K) {
    int bh   = blockIdx.x >> 4;
    int tile = blockIdx.x & 15;
    int b = bh >> 3, h = bh & 7;
    int tid = threadIdx.x;
    int kx = tid & 31;        // k lane: owns k = kx + 32*j, j=0..3
    int uy = tid >> 5;        // u group: owns u = uy*5 + i, i=0..4

    __shared__ float Qs[U_ * D_];       // 10 KB
    __shared__ float Ks[128 * 65];      // 33.3 KB

    for (int i = tid; i < U_ * D_; i += 256) {
        int u = i >> 6, d = i & 63;
        int qi = g_top[bh * U_ + u];
        Qs[i] = Q[((size_t)(b * L_ + qi) * H_ + h) * D_ + d] * SCALE;
    }
    int k0 = tile * 128;
    for (int i = tid; i < 128 * D_; i += 256) {
        int kk = i >> 6, d = i & 63;
        Ks[kk * 65 + d] = K[((size_t)(b * L_ + k0 + kk) * H_ + h) * D_ + d];
    }
    __syncthreads();

    float acc[20];
#pragma unroll
    for (int a = 0; a < 20; a++) acc[a] = 0.f;

    for (int d4 = 0; d4 < 16; d4++) {
        float4 q4[5];
#pragma unroll
        for (int i = 0; i < 5; i++)
            q4[i] = *(const float4*)(Qs + (uy * 5 + i) * 64 + d4 * 4);
#pragma unroll
        for (int j = 0; j < 4; j++) {
            const float* kp = Ks + (kx + 32 * j) * 65 + d4 * 4;
            float k0v = kp[0], k1v = kp[1], k2v = kp[2], k3v = kp[3];
#pragma unroll
            for (int i = 0; i < 5; i++)
                acc[i * 4 + j] += q4[i].x * k0v + q4[i].y * k1v
                                + q4[i].z * k2v + q4[i].w * k3v;
        }
    }
#pragma unroll
    for (int i = 0; i < 5; i++) {
        int u = uy * 5 + i;
        float* dst = g_S + ((size_t)(bh * U_ + u)) * L_ + k0 + kx;
#pragma unroll
        for (int j = 0; j < 4; j++)
            dst[32 * j] = acc[i * 4 + j];
    }
}

// ---------------------------------------------------------------------------
// K3b: per row (bh,u): softmax + suffix-sum, normalized, in place.
// Register-resident: float4 loads, warp shuffles, 2 barriers total.
// ---------------------------------------------------------------------------
__global__ __launch_bounds__(256) void k3b_scan() {
    int row = blockIdx.x, tid = threadIdx.x;
    int lane = tid & 31, w = tid >> 5;
    float4* p4 = (float4*)(g_S + (size_t)row * L_) + tid * 2;
    float4 a = p4[0], b = p4[1];

    float m = fmaxf(fmaxf(fmaxf(a.x, a.y), fmaxf(a.z, a.w)),
                    fmaxf(fmaxf(b.x, b.y), fmaxf(b.z, b.w)));
#pragma unroll
    for (int off = 16; off > 0; off >>= 1)
        m = fmaxf(m, __shfl_xor_sync(0xffffffffu, m, off));
    __shared__ float wmax[8], wsum[8];
    if (lane == 0) wmax[w] = m;
    __syncthreads();
    float rm = wmax[0];
#pragma unroll
    for (int i = 1; i < 8; i++) rm = fmaxf(rm, wmax[i]);

    // exp + suffix within the thread's 8 elements (descending j)
    float s = __expf(b.w - rm); b.w = s;
    s += __expf(b.z - rm); b.z = s;
    s += __expf(b.y - rm); b.y = s;
    s += __expf(b.x - rm); b.x = s;
    s += __expf(a.w - rm); a.w = s;
    s += __expf(a.z - rm); a.z = s;
    s += __expf(a.y - rm); a.y = s;
    s += __expf(a.x - rm); a.x = s;
    float chunk = s;

    // warp inclusive suffix scan of chunk sums
    float c = chunk;
#pragma unroll
    for (int off = 1; off < 32; off <<= 1) {
        float vv = __shfl_down_sync(0xffffffffu, c, off);
        if (lane + off < 32) c += vv;
    }
    if (lane == 0) wsum[w] = c;           // warp total
    __syncthreads();
    float total = 0.f, after = 0.f;
#pragma unroll
    for (int i = 7; i >= 0; i--) { total += wsum[i]; if (i > w) after += wsum[i]; }
    float add  = (c - chunk) + after;     // suffix strictly after this thread's 8
    float invZ = 1.0f / total;

    a.x = (a.x + add) * invZ; a.y = (a.y + add) * invZ;
    a.z = (a.z + add) * invZ; a.w = (a.w + add) * invZ;
    b.x = (b.x + add) * invZ; b.y = (b.y + add) * invZ;
    b.z = (b.z + add) * invZ; b.w = (b.w + add) * invZ;
    p4[0] = a; p4[1] = b;
}

// ---------------------------------------------------------------------------
// K3c: context partials: C_part[tile] = S[:, ktile] @ V[ktile, :]
// Register tiling: 16 d-lanes (4 d via LDS.128) x 8 u-threads (5 u each).
// ---------------------------------------------------------------------------
__global__ __launch_bounds__(128) void k3c_ctx(const float* __restrict__ V) {
    int bh   = blockIdx.x >> 3;
    int tile = blockIdx.x & 7;
    int b = bh >> 3, h = bh & 7;
    int tid = threadIdx.x;
    int dx = tid & 15;        // owns d = dx*4 .. dx*4+3
    int uy = tid >> 4;        // owns u = uy*5 + i, i=0..4

    __shared__ float Vs[64 * 64];   // 16 KB
    __shared__ float Ss[U_ * 64];   // 10 KB

    float4 acc[5];
#pragma unroll
    for (int i = 0; i < 5; i++) acc[i] = make_float4(0.f, 0.f, 0.f, 0.f);

    for (int c = 0; c < 4; c++) {
        int k0 = tile * 256 + c * 64;
        __syncthreads();
        for (int i = tid; i < 64 * 16; i += 128) {
            int kk = i >> 4, f = i & 15;
            float4 vv = *((const float4*)(V + ((size_t)(b * L_ + k0 + kk) * H_ + h) * D_) + f);
            *(float4*)(Vs + kk * 64 + f * 4) = vv;
        }
        for (int i = tid; i < U_ * 64; i += 128) {
            int u = i >> 6, kk = i & 63;
            Ss[i] = g_S[((size_t)(bh * U_ + u)) * L_ + k0 + kk];
        }
        __syncthreads();
        for (int k = 0; k < 64; k++) {
            float4 v = *(const float4*)(Vs + k * 64 + dx * 4);
#pragma unroll
            for (int i = 0; i < 5; i++) {
                float sv = Ss[(uy * 5 + i) * 64 + k];
                acc[i].x += sv * v.x; acc[i].y += sv * v.y;
                acc[i].z += sv * v.z; acc[i].w += sv * v.w;
            }
        }
    }
#pragma unroll
    for (int i = 0; i < 5; i++) {
        int u = uy * 5 + i;
        *(float4*)(g_C + (size_t)tile * (BH * U_ * D_) + (bh * U_ + u) * D_ + dx * 4) = acc[i];
    }
}

// ---------------------------------------------------------------------------
// K3r: reduce partials -> out
// ---------------------------------------------------------------------------
__global__ __launch_bounds__(256) void k3r_reduce(float* __restrict__ out) {
    int i = blockIdx.x * 256 + threadIdx.x;
    float s = 0.f;
#pragma unroll
    for (int t = 0; t < NT3; t++) s += g_C[(size_t)t * (BH * U_ * D_) + i];
    out[i] = s;
}

// ---------------------------------------------------------------------------
extern "C" void kernel_launch(void* const* d_in, const int* in_sizes, int n_in,
                              void* d_out, int out_size) {
    const float* Q   = (const float*)d_in[0];
    const float* K   = (const float*)d_in[1];
    const float* V   = (const float*)d_in[2];
    const int*   idx = (const int*)d_in[3];
    float* out = (float*)d_out;

    cudaFuncSetAttribute(k1_sample, cudaFuncAttributeMaxDynamicSharedMemorySize,
                         CROWS * PADW * 4);

    k0_prep<<<(L_ + 255) / 256, 256>>>(idx);
    k1_sample<<<BH * NCHUNK, 1024, CROWS * PADW * 4>>>(Q, K);
    k2_topk<<<BH, 256>>>();
    k3a_scores<<<BH * 16, 256>>>(Q, K);
    k3b_scan<<<BH * U_, 256>>>();
    k3c_ctx<<<BH * NT3, 128>>>(V);
    k3r_reduce<<<(BH * U_ * D_) / 256, 256>>>(out);
}